// round 8
// baseline (speedup 1.0000x reference)
#include <cuda_runtime.h>
#include <cuda_fp16.h>
#include <math.h>

#define Nn 100000
#define Ee 1200000

// ---------------- persistent device scratch (no runtime allocation) ----------------
__device__ int    d_is64;          // 1 if edge indices are int64, 0 if int32
__device__ int    d_cnt[2][Nn];
__device__ int    d_rowstart[2][Nn + 1];
__device__ int    d_cursor[2][Nn];
__device__ int    d_csr[2][Ee];
__device__ float  d_inv[2][Nn];
__device__ int    d_bsum[2][128];
__device__ int    d_bscan[2][128];
__device__ float4 d_P[Nn * 32];    // pos-mean-agg (fp32, 128 per node)
__device__ float4 d_Q[Nn * 32];    // neg-mean-agg
__device__ float4 d_Z1[Nn * 32];   // z after round 0 (fp32)
__device__ float4 d_Z2[Nn * 32];   // z after round 1 (fp32)
__device__ uint4  d_Xh [Nn * 16];  // fp16 mirror of x   (8 halfs per uint4)
__device__ uint4  d_Zh1[Nn * 16];  // fp16 mirror of z1
__device__ uint4  d_Zh2[Nn * 16];  // fp16 mirror of z2

// ---------------- f32x2 packed-FMA helpers ----------------
__device__ __forceinline__ unsigned long long pack2(float lo, float hi) {
    unsigned long long r;
    asm("mov.b64 %0, {%1, %2};" : "=l"(r) : "f"(lo), "f"(hi));
    return r;
}
__device__ __forceinline__ void fma2(unsigned long long& d, unsigned long long a,
                                     unsigned long long b) {
    asm("fma.rn.f32x2 %0, %1, %2, %0;" : "+l"(d) : "l"(a), "l"(b));
}
__device__ __forceinline__ float2 unpack2(unsigned long long v) {
    float2 f;
    asm("mov.b64 {%0, %1}, %2;" : "=f"(f.x), "=f"(f.y) : "l"(v));
    return f;
}

// ---------------- dtype detection (int64 vs int32 edge indices) ----------------
__global__ void k_detect(const int* __restrict__ pe) {
    __shared__ int nz;
    if (threadIdx.x == 0) nz = 0;
    __syncthreads();
    for (int t = threadIdx.x; t < 1024; t += blockDim.x) {
        if (pe[2 * t + 1] != 0) nz = 1;
    }
    __syncthreads();
    if (threadIdx.x == 0) d_is64 = (nz == 0) ? 1 : 0;
}

__device__ __forceinline__ int edge_at(const void* p, long i, int is64) {
    return is64 ? (int)((const long long*)p)[i] : ((const int*)p)[i];
}

// ---------------- fp32 -> fp16 mirror of x ----------------
__global__ void k_x2h(const float4* __restrict__ x) {
    long i = (long)blockIdx.x * blockDim.x + threadIdx.x;
    if (i < (long)Nn * 32) {
        float4 v = x[i];
        __half2 a = __floats2half2_rn(v.x, v.y);
        __half2 b = __floats2half2_rn(v.z, v.w);
        uint2 o;
        o.x = *(const unsigned*)&a;
        o.y = *(const unsigned*)&b;
        ((uint2*)d_Xh)[i] = o;
    }
}

// ---------------- CSR build ----------------
__global__ void k_zero() {
    int i = blockIdx.x * blockDim.x + threadIdx.x;
    if (i < 2 * Nn) (&d_cnt[0][0])[i] = 0;
}

__global__ void k_hist(const void* __restrict__ pe, const void* __restrict__ ne) {
    int is64 = d_is64;
    int i = blockIdx.x * blockDim.x + threadIdx.x;
    if (i < Ee) {
        int dst = edge_at(pe, (long)Ee + i, is64);
        if ((unsigned)dst < Nn) atomicAdd(&d_cnt[0][dst], 1);
    } else if (i < 2 * Ee) {
        int dst = edge_at(ne, (long)i, is64);
        if ((unsigned)dst < Nn) atomicAdd(&d_cnt[1][dst], 1);
    }
}

__global__ void k_scan1() {
    __shared__ int sh[1024];
    int L = blockIdx.y;
    int i = blockIdx.x * 1024 + threadIdx.x;
    int v = (i < Nn) ? d_cnt[L][i] : 0;
    sh[threadIdx.x] = v;
    __syncthreads();
    for (int off = 1; off < 1024; off <<= 1) {
        int t = (threadIdx.x >= off) ? sh[threadIdx.x - off] : 0;
        __syncthreads();
        sh[threadIdx.x] += t;
        __syncthreads();
    }
    if (i < Nn) d_rowstart[L][i] = sh[threadIdx.x] - v;
    if (threadIdx.x == 1023) d_bsum[L][blockIdx.x] = sh[1023];
}

__global__ void k_scan2() {
    __shared__ int sh[128];
    int L = blockIdx.y;
    int v = (threadIdx.x < 98) ? d_bsum[L][threadIdx.x] : 0;
    sh[threadIdx.x] = v;
    __syncthreads();
    for (int off = 1; off < 128; off <<= 1) {
        int t = (threadIdx.x >= off) ? sh[threadIdx.x - off] : 0;
        __syncthreads();
        sh[threadIdx.x] += t;
        __syncthreads();
    }
    d_bscan[L][threadIdx.x] = sh[threadIdx.x] - v;
}

__global__ void k_scan3() {
    int L = blockIdx.y;
    int i = blockIdx.x * blockDim.x + threadIdx.x;
    if (i < Nn) {
        int rs = d_rowstart[L][i] + d_bscan[L][i >> 10];
        d_rowstart[L][i] = rs;
        d_cursor[L][i]   = rs;
        int c = d_cnt[L][i];
        d_inv[L][i] = 1.0f / (float)(c > 0 ? c : 1);
    }
    if (i == Nn - 1) d_rowstart[L][Nn] = d_rowstart[L][i] + d_cnt[L][i];
}

__global__ void k_fill(const void* __restrict__ pe, const void* __restrict__ ne) {
    int is64 = d_is64;
    int i = blockIdx.x * blockDim.x + threadIdx.x;
    if (i < Ee) {
        int s = edge_at(pe, (long)i, is64);
        int d = edge_at(pe, (long)Ee + i, is64);
        if ((unsigned)d < Nn && (unsigned)s < Nn)
            d_csr[0][atomicAdd(&d_cursor[0][d], 1)] = s;
    } else if (i < 2 * Ee) {
        long k = i - Ee;
        int s = edge_at(ne, k, is64);
        int d = edge_at(ne, (long)i, is64);
        if ((unsigned)d < Nn && (unsigned)s < Nn)
            d_csr[1][atomicAdd(&d_cursor[1][d], 1)] = s;
    }
}

// ---------------- per-destination mean aggregation (fp16 gathers, fp32 accum) ---
// 16 lanes x uint4 (16B) cover one 256B fp16 row -> 2 nodes per warp.
// grid (Nn/8, 2), block 128 = 4 warps = 8 nodes per block.
__global__ void k_agg(int io) {
    const uint4* __restrict__ Zh = (io == 0) ? d_Xh : (io == 1 ? d_Zh1 : d_Zh2);
    int L    = blockIdx.y;
    int lane = threadIdx.x & 31;
    int sub  = lane >> 4;                 // node-within-warp (0/1)
    int l16  = lane & 15;                 // uint4 column within row
    int node = blockIdx.x * 8 + (threadIdx.x >> 5) * 2 + sub;
    int s   = d_rowstart[L][node];
    int len = d_rowstart[L][node + 1] - s;
    int mlen = max(len, __shfl_xor_sync(0xffffffffu, len, 16));
    const int* __restrict__ csr = d_csr[L];

    float a0 = 0.f, a1 = 0.f, a2 = 0.f, a3 = 0.f;
    float a4 = 0.f, a5 = 0.f, a6 = 0.f, a7 = 0.f;
    for (int k = 0; k < mlen; k += 4) {
        #pragma unroll
        for (int u = 0; u < 4; u++) {
            if (k + u < len) {
                int src = csr[s + k + u];
                uint4 v = Zh[src * 16 + l16];
                float2 f0 = __half22float2(*(const __half2*)&v.x);
                float2 f1 = __half22float2(*(const __half2*)&v.y);
                float2 f2 = __half22float2(*(const __half2*)&v.z);
                float2 f3 = __half22float2(*(const __half2*)&v.w);
                a0 += f0.x; a1 += f0.y; a2 += f1.x; a3 += f1.y;
                a4 += f2.x; a5 += f2.y; a6 += f3.x; a7 += f3.y;
            }
        }
    }
    float iv = d_inv[L][node];
    float4* out = (L ? d_Q : d_P) + (long)node * 32 + l16 * 2;
    out[0] = make_float4(a0 * iv, a1 * iv, a2 * iv, a3 * iv);
    out[1] = make_float4(a4 * iv, a5 * iv, a6 * iv, a7 * iv);
}

// ---------------- fused dual-GEMM + bias + tanh (f32x2 packed FMA) ----------------
template<int KA, int KB>
__global__ __launch_bounds__(128)
void k_transform(const float4* __restrict__ x_or_z, float4* __restrict__ ext_out, int io,
                 const float4* __restrict__ W1p, const float4* __restrict__ W1n,
                 const float4* __restrict__ W2p, const float4* __restrict__ W2n,
                 const float* __restrict__ bpv, const float* __restrict__ bnv)
{
    constexpr int KTOT = KA + KB;
    constexpr int NCH  = KTOT / 16;
    __shared__ float4     Wsh[16][32];        // 8 KB
    __shared__ ulonglong2 Adup[64][2][8];     // 16 KB: [n][h][k-pair], dup'd f32x2

    const float4* __restrict__ Zin = (io == 0) ? x_or_z
                                   : (io == 1 ? (const float4*)d_Z1 : (const float4*)d_Z2);
    float4* __restrict__ Zout = (io == 0) ? (float4*)d_Z1
                              : (io == 1 ? (float4*)d_Z2 : ext_out);
    uint2* __restrict__ Zhout = (io == 0) ? (uint2*)d_Zh1
                              : (io == 1 ? (uint2*)d_Zh2 : (uint2*)0);

    const int tid  = threadIdx.x;
    const int ct   = tid & 31;
    const int g    = tid >> 5;
    const int h    = ct >> 4;
    const int base = blockIdx.x * 64;

    unsigned long long acc[16][2];
    {
        int j0 = ct * 4;
        float b0 = (j0 + 0 < 64) ? bpv[j0 + 0] : bnv[j0 - 64];
        float b1 = (j0 + 1 < 64) ? bpv[j0 + 1] : bnv[j0 - 63];
        float b2 = (j0 + 2 < 64) ? bpv[j0 + 2] : bnv[j0 - 62];
        float b3 = (j0 + 3 < 64) ? bpv[j0 + 3] : bnv[j0 - 61];
        unsigned long long p01 = pack2(b0, b1), p23 = pack2(b2, b3);
        #pragma unroll
        for (int m = 0; m < 16; m++) { acc[m][0] = p01; acc[m][1] = p23; }
    }

    for (int c = 0; c < NCH; c++) {
        __syncthreads();
        // stage W chunk rows [c*16, c*16+16)
        for (int f = tid; f < 16 * 32; f += 128) {
            int jq = f & 31, r = f >> 5;
            int k  = c * 16 + r;
            float4 v;
            if (jq < 16) v = (k < KA) ? W1p[k * 16 + jq]      : W2p[(k - KA) * 16 + jq];
            else         v = (k < KA) ? W1n[k * 16 + jq - 16] : W2n[(k - KA) * 16 + jq - 16];
            Wsh[r][jq] = v;
        }
        // stage Adup: 64 nodes x 2 halves x 4 float4-k per chunk
        for (int f = tid; f < 512; f += 128) {
            int kk4 = f & 3;
            int hh  = (f >> 2) & 1;
            int n   = f >> 3;
            int i   = base + n;
            int KQg = c * 4 + kk4;
            float4 v = make_float4(0.f, 0.f, 0.f, 0.f);
            if (i < Nn) {
                const float4* ap;
                if (KTOT == 256) {                    // round 0
                    if (KQg < 32) ap = (hh ? d_Q : d_P) + (long)i * 32 + KQg;
                    else          ap = Zin + (long)i * 32 + (KQg - 32);
                } else {                              // rounds 1+
                    if (KQg < 16)      ap = d_P + (long)i * 32 + hh * 16 + KQg;
                    else if (KQg < 32) ap = d_Q + (long)i * 32 + (1 - hh) * 16 + (KQg - 16);
                    else               ap = Zin + (long)i * 32 + hh * 16 + (KQg - 32);
                }
                v = *ap;
            }
            ulonglong2 p0, p1;
            p0.x = pack2(v.x, v.x); p0.y = pack2(v.y, v.y);
            p1.x = pack2(v.z, v.z); p1.y = pack2(v.w, v.w);
            Adup[n][hh][kk4 * 2 + 0] = p0;
            Adup[n][hh][kk4 * 2 + 1] = p1;
        }
        __syncthreads();

        #pragma unroll
        for (int kq = 0; kq < 4; kq++) {
            ulonglong2 w0 = *(const ulonglong2*)&Wsh[4 * kq + 0][ct];
            ulonglong2 w1 = *(const ulonglong2*)&Wsh[4 * kq + 1][ct];
            ulonglong2 w2 = *(const ulonglong2*)&Wsh[4 * kq + 2][ct];
            ulonglong2 w3 = *(const ulonglong2*)&Wsh[4 * kq + 3][ct];
            #pragma unroll
            for (int m = 0; m < 16; m++) {
                ulonglong2 a01 = Adup[g * 16 + m][h][kq * 2 + 0];
                ulonglong2 a23 = Adup[g * 16 + m][h][kq * 2 + 1];
                fma2(acc[m][0], a01.x, w0.x);
                fma2(acc[m][1], a01.x, w0.y);
                fma2(acc[m][0], a01.y, w1.x);
                fma2(acc[m][1], a01.y, w1.y);
                fma2(acc[m][0], a23.x, w2.x);
                fma2(acc[m][1], a23.x, w2.y);
                fma2(acc[m][0], a23.y, w3.x);
                fma2(acc[m][1], a23.y, w3.y);
            }
        }
    }

    #pragma unroll
    for (int m = 0; m < 16; m++) {
        int i = base + g * 16 + m;
        if (i < Nn) {
            float2 r01 = unpack2(acc[m][0]);
            float2 r23 = unpack2(acc[m][1]);
            float t0 = tanhf(r01.x), t1 = tanhf(r01.y);
            float t2 = tanhf(r23.x), t3 = tanhf(r23.y);
            Zout[(long)i * 32 + ct] = make_float4(t0, t1, t2, t3);
            if (Zhout) {
                __half2 a = __floats2half2_rn(t0, t1);
                __half2 b = __floats2half2_rn(t2, t3);
                uint2 o;
                o.x = *(const unsigned*)&a;
                o.y = *(const unsigned*)&b;
                Zhout[(long)i * 32 + ct] = o;
            }
        }
    }
}

// ---------------- launch (kernel launches only; graph-capturable) ----------------
extern "C" void kernel_launch(void* const* d_in, const int* in_sizes, int n_in,
                              void* d_out, int out_size) {
    const float* x      = (const float*)d_in[0];
    const void*  pe     = d_in[1];     // edge indices: int32 or int64, detected on device
    const void*  ne     = d_in[2];
    const float4* Wp_l  = (const float4*)d_in[3];
    const float4* Wp_r  = (const float4*)d_in[4];
    const float*  bp    = (const float*)d_in[5];
    const float4* Wn_l  = (const float4*)d_in[6];
    const float4* Wn_r  = (const float4*)d_in[7];
    const float*  bn    = (const float*)d_in[8];
    const float4* Wl_pos = (const float4*)d_in[9];
    const float4* Wr_pos = (const float4*)d_in[10];
    const float*  b_pos  = (const float*)d_in[11];
    const float4* Wl_neg = (const float4*)d_in[12];
    const float4* Wr_neg = (const float4*)d_in[13];
    const float*  b_neg  = (const float*)d_in[14];

    const float4* xin  = (const float4*)x;
    float4*       outp = (float4*)d_out;

    // CSR build + fp16 mirror of x
    k_detect<<<1, 256>>>((const int*)pe);
    k_x2h  <<<(Nn * 32 + 255) / 256, 256>>>(xin);
    k_zero <<<(2 * Nn + 255) / 256, 256>>>();
    k_hist <<<(2 * Ee + 255) / 256, 256>>>(pe, ne);
    k_scan1<<<dim3(98, 2), 1024>>>();
    k_scan2<<<dim3(1, 2), 128>>>();
    k_scan3<<<dim3((Nn + 255) / 256, 2), 256>>>();
    k_fill <<<(2 * Ee + 255) / 256, 256>>>(pe, ne);

    const int TGRID = (Nn + 63) / 64;
    const int AGRID = Nn / 8;   // 12500

    // round 0
    k_agg<<<dim3(AGRID, 2), 128>>>(0);
    k_transform<128, 128><<<TGRID, 128>>>(xin, outp, 0, Wp_l, Wn_l, Wp_r, Wn_r, bp, bn);

    // round 1 (hidden layer l=0)
    k_agg<<<dim3(AGRID, 2), 128>>>(1);
    k_transform<128, 64><<<TGRID, 128>>>(xin, outp, 1,
        Wl_pos, Wl_neg, Wr_pos, Wr_neg, b_pos, b_neg);

    // round 2 (hidden layer l=1) -> writes d_out
    k_agg<<<dim3(AGRID, 2), 128>>>(2);
    k_transform<128, 64><<<TGRID, 128>>>(xin, outp, 2,
        Wl_pos + 2048, Wl_neg + 2048, Wr_pos + 1024, Wr_neg + 1024, b_pos + 64, b_neg + 64);
}

// round 9
// speedup vs baseline: 1.7254x; 1.7254x over previous
#include <cuda_runtime.h>
#include <cuda_fp16.h>
#include <math.h>

#define Nn 100000
#define Ee 1200000

// ---------------- persistent device scratch (no runtime allocation) ----------------
__device__ int    d_is64;
__device__ int    d_cnt[2][Nn];
__device__ int    d_rowstart[2][Nn + 1];
__device__ int    d_cursor[2][Nn];
__device__ int    d_csr[2][Ee];
__device__ float  d_inv[2][Nn];
__device__ int    d_bsum[2][128];
__device__ int    d_bscan[2][128];
__device__ uint2  d_Xh [Nn * 32];   // fp16 x   (4 halfs per uint2, 128/node)
__device__ uint2  d_Zh1[Nn * 32];   // fp16 z after round 0
__device__ uint2  d_Zh2[Nn * 32];   // fp16 z after round 1
__device__ uint2  d_Ph [Nn * 32];   // fp16 pos-mean-agg
__device__ uint2  d_Qh [Nn * 32];   // fp16 neg-mean-agg
__device__ __half d_Wt[3 * 2 * 128 * 256];  // [round][hi/res][n=128][k<=256] fp16
__device__ float  d_bias[3 * 128];

// ---------------- helpers ----------------
__device__ __forceinline__ unsigned smem_u32(const void* p) {
    unsigned r;
    asm("{ .reg .u64 t; cvta.to.shared.u64 t, %1; cvt.u32.u64 %0, t; }" : "=r"(r) : "l"(p));
    return r;
}
__device__ __forceinline__ void ldsm4(unsigned* r, unsigned addr) {
    asm volatile("ldmatrix.sync.aligned.m8n8.x4.shared.b16 {%0,%1,%2,%3},[%4];"
        : "=r"(r[0]), "=r"(r[1]), "=r"(r[2]), "=r"(r[3]) : "r"(addr));
}
__device__ __forceinline__ void mma16816(float* c, const unsigned* a, unsigned b0, unsigned b1) {
    asm volatile("mma.sync.aligned.m16n8k16.row.col.f32.f16.f16.f32 "
        "{%0,%1,%2,%3},{%4,%5,%6,%7},{%8,%9},{%0,%1,%2,%3};"
        : "+f"(c[0]), "+f"(c[1]), "+f"(c[2]), "+f"(c[3])
        : "r"(a[0]), "r"(a[1]), "r"(a[2]), "r"(a[3]), "r"(b0), "r"(b1));
}

// ---------------- dtype detection (int64 vs int32 edge indices) ----------------
__global__ void k_detect(const int* __restrict__ pe) {
    __shared__ int nz;
    if (threadIdx.x == 0) nz = 0;
    __syncthreads();
    for (int t = threadIdx.x; t < 1024; t += blockDim.x) {
        if (pe[2 * t + 1] != 0) nz = 1;
    }
    __syncthreads();
    if (threadIdx.x == 0) d_is64 = (nz == 0) ? 1 : 0;
}
__device__ __forceinline__ int edge_at(const void* p, long i, int is64) {
    return is64 ? (int)((const long long*)p)[i] : ((const int*)p)[i];
}

// ---------------- fp32 -> fp16 mirror of x ----------------
__global__ void k_x2h(const float4* __restrict__ x) {
    long i = (long)blockIdx.x * blockDim.x + threadIdx.x;
    if (i < (long)Nn * 32) {
        float4 v = x[i];
        __half2 a = __floats2half2_rn(v.x, v.y);
        __half2 b = __floats2half2_rn(v.z, v.w);
        uint2 o;
        o.x = *(const unsigned*)&a;
        o.y = *(const unsigned*)&b;
        d_Xh[i] = o;
    }
}

// ---------------- weight prep: combined fp16 hi/residual, n-major layout ----------
// Wt[r][pass][n][k]: rows k<128 = agg weight W_l, k>=128 = self weight W_r;
// n<64 -> pos weights, n>=64 -> neg. K_eff: round0=256, rounds1+=192.
__global__ void k_wprep(const float* __restrict__ Wp_l, const float* __restrict__ Wp_r,
                        const float* __restrict__ bp,
                        const float* __restrict__ Wn_l, const float* __restrict__ Wn_r,
                        const float* __restrict__ bn,
                        const float* __restrict__ Wl_pos, const float* __restrict__ Wr_pos,
                        const float* __restrict__ b_pos,
                        const float* __restrict__ Wl_neg, const float* __restrict__ Wr_neg,
                        const float* __restrict__ b_neg) {
    int idx = blockIdx.x * blockDim.x + threadIdx.x;
    if (idx >= 3 * 128 * 256) return;
    int k = idx & 255, n = (idx >> 8) & 127, r = idx >> 15;
    int keff = (r == 0) ? 256 : 192;
    float v = 0.f;
    int jl = n & 63;
    bool neg = n >= 64;
    if (k < keff) {
        if (r == 0) {
            if (k < 128) v = (neg ? Wn_l : Wp_l)[k * 64 + jl];
            else         v = (neg ? Wn_r : Wp_r)[(k - 128) * 64 + jl];
        } else {
            int l = r - 1;
            if (k < 128) v = (neg ? Wl_neg : Wl_pos)[l * 128 * 64 + k * 64 + jl];
            else         v = (neg ? Wr_neg : Wr_pos)[l * 64 * 64 + (k - 128) * 64 + jl];
        }
    }
    __half hi = __float2half_rn(v);
    __half re = __float2half_rn(v - __half2float(hi));
    d_Wt[((r * 2 + 0) * 128 + n) * 256 + k] = hi;
    d_Wt[((r * 2 + 1) * 128 + n) * 256 + k] = re;
    if (k == 0) {
        float b = (r == 0) ? (neg ? bn[jl] : bp[jl])
                           : (neg ? b_neg[(r - 1) * 64 + jl] : b_pos[(r - 1) * 64 + jl]);
        d_bias[r * 128 + n] = b;
    }
}

// ---------------- CSR build ----------------
__global__ void k_zero() {
    int i = blockIdx.x * blockDim.x + threadIdx.x;
    if (i < 2 * Nn) (&d_cnt[0][0])[i] = 0;
}
__global__ void k_hist(const void* __restrict__ pe, const void* __restrict__ ne) {
    int is64 = d_is64;
    int i = blockIdx.x * blockDim.x + threadIdx.x;
    if (i < Ee) {
        int dst = edge_at(pe, (long)Ee + i, is64);
        if ((unsigned)dst < Nn) atomicAdd(&d_cnt[0][dst], 1);
    } else if (i < 2 * Ee) {
        int dst = edge_at(ne, (long)i, is64);
        if ((unsigned)dst < Nn) atomicAdd(&d_cnt[1][dst], 1);
    }
}
__global__ void k_scan1() {
    __shared__ int sh[1024];
    int L = blockIdx.y;
    int i = blockIdx.x * 1024 + threadIdx.x;
    int v = (i < Nn) ? d_cnt[L][i] : 0;
    sh[threadIdx.x] = v;
    __syncthreads();
    for (int off = 1; off < 1024; off <<= 1) {
        int t = (threadIdx.x >= off) ? sh[threadIdx.x - off] : 0;
        __syncthreads();
        sh[threadIdx.x] += t;
        __syncthreads();
    }
    if (i < Nn) d_rowstart[L][i] = sh[threadIdx.x] - v;
    if (threadIdx.x == 1023) d_bsum[L][blockIdx.x] = sh[1023];
}
__global__ void k_scan2() {
    __shared__ int sh[128];
    int L = blockIdx.y;
    int v = (threadIdx.x < 98) ? d_bsum[L][threadIdx.x] : 0;
    sh[threadIdx.x] = v;
    __syncthreads();
    for (int off = 1; off < 128; off <<= 1) {
        int t = (threadIdx.x >= off) ? sh[threadIdx.x - off] : 0;
        __syncthreads();
        sh[threadIdx.x] += t;
        __syncthreads();
    }
    d_bscan[L][threadIdx.x] = sh[threadIdx.x] - v;
}
__global__ void k_scan3() {
    int L = blockIdx.y;
    int i = blockIdx.x * blockDim.x + threadIdx.x;
    if (i < Nn) {
        int rs = d_rowstart[L][i] + d_bscan[L][i >> 10];
        d_rowstart[L][i] = rs;
        d_cursor[L][i]   = rs;
        int c = d_cnt[L][i];
        d_inv[L][i] = 1.0f / (float)(c > 0 ? c : 1);
    }
    if (i == Nn - 1) d_rowstart[L][Nn] = d_rowstart[L][i] + d_cnt[L][i];
}
__global__ void k_fill(const void* __restrict__ pe, const void* __restrict__ ne) {
    int is64 = d_is64;
    int i = blockIdx.x * blockDim.x + threadIdx.x;
    if (i < Ee) {
        int s = edge_at(pe, (long)i, is64);
        int d = edge_at(pe, (long)Ee + i, is64);
        if ((unsigned)d < Nn && (unsigned)s < Nn)
            d_csr[0][atomicAdd(&d_cursor[0][d], 1)] = s;
    } else if (i < 2 * Ee) {
        long k = i - Ee;
        int s = edge_at(ne, k, is64);
        int d = edge_at(ne, (long)i, is64);
        if ((unsigned)d < Nn && (unsigned)s < Nn)
            d_csr[1][atomicAdd(&d_cursor[1][d], 1)] = s;
    }
}

// ---------------- per-destination mean aggregation (fp16 in, fp16 out) ----------
// warp per dst node, lane = 4 halfs (uint2).  (R7 structure, proven fastest.)
__global__ void k_agg(int io) {
    const uint2* __restrict__ Zh = (io == 0) ? d_Xh : (io == 1 ? d_Zh1 : d_Zh2);
    int L    = blockIdx.y;
    int node = blockIdx.x * 4 + (threadIdx.x >> 5);
    int lane = threadIdx.x & 31;
    int s = d_rowstart[L][node];
    int e = d_rowstart[L][node + 1];
    const int* __restrict__ csr = d_csr[L];
    float ax = 0.f, ay = 0.f, az = 0.f, aw = 0.f;
    int j = s;
    for (; j + 4 <= e; j += 4) {
        int s0 = csr[j], s1 = csr[j + 1], s2 = csr[j + 2], s3 = csr[j + 3];
        uint2 v0 = Zh[s0 * 32 + lane];
        uint2 v1 = Zh[s1 * 32 + lane];
        uint2 v2 = Zh[s2 * 32 + lane];
        uint2 v3 = Zh[s3 * 32 + lane];
        #pragma unroll
        for (int t = 0; t < 4; t++) {
            uint2 v = (t == 0) ? v0 : (t == 1) ? v1 : (t == 2) ? v2 : v3;
            float2 f01 = __half22float2(*(const __half2*)&v.x);
            float2 f23 = __half22float2(*(const __half2*)&v.y);
            ax += f01.x; ay += f01.y; az += f23.x; aw += f23.y;
        }
    }
    for (; j < e; j++) {
        uint2 v = Zh[csr[j] * 32 + lane];
        float2 f01 = __half22float2(*(const __half2*)&v.x);
        float2 f23 = __half22float2(*(const __half2*)&v.y);
        ax += f01.x; ay += f01.y; az += f23.x; aw += f23.y;
    }
    float iv = d_inv[L][node];
    __half2 o0 = __floats2half2_rn(ax * iv, ay * iv);
    __half2 o1 = __floats2half2_rn(az * iv, aw * iv);
    uint2 o;
    o.x = *(const unsigned*)&o0;
    o.y = *(const unsigned*)&o1;
    (L ? d_Qh : d_Ph)[node * 32 + lane] = o;
}

// ---------------- fused GEMM + bias + tanh via mma.sync (fp16, hi/res W) --------
// Block 256 thr = 8 warps; M-tile 64 nodes; N = 128 combined cols.
// Warp w: half h = w>>4? -> h = w/4; strips: 2 x n8 per warp.
// A_cat per half: round0: [P|x](256) / [Q|x]; rounds: [P-slice|Q-slice|z-slice](192).
template<int R>
__global__ __launch_bounds__(256)
void k_mm(float* __restrict__ outp) {
    constexpr int KEFF = (R == 0) ? 256 : 192;
    __shared__ __half Ash[2][64][136];    // 34.8 KB, +8 pad for ldmatrix conflicts

    const int tid  = threadIdx.x;
    const int w    = tid >> 5;
    const int lane = tid & 31;
    const int h    = w >> 2;          // 0: pos cols, 1: neg cols
    const int wl   = w & 3;           // 16-col group within half
    const int grp  = lane >> 2;
    const int tg   = lane & 3;
    const int base = blockIdx.x * 64;

    float acc[4][2][4];
    #pragma unroll
    for (int mt = 0; mt < 4; mt++)
        #pragma unroll
        for (int sp = 0; sp < 2; sp++)
            #pragma unroll
            for (int c = 0; c < 4; c++) acc[mt][sp][c] = 0.f;

    #pragma unroll
    for (int st = 0; st < 2; st++) {
        const int ks = st * 128;
        const int SL = (KEFF - ks < 128) ? (KEFF - ks) : 128;
        if (SL <= 0) break;
        __syncthreads();
        // stage A (both halves) for k in [ks, ks+SL)
        const int nq = SL / 4;                    // uint2 per (h, m)
        for (int f = tid; f < 2 * 64 * nq; f += 256) {
            int kq   = f % nq;
            int rest = f / nq;
            int hh   = rest & 1;
            int m    = rest >> 1;
            int i    = base + m;
            int kg   = ks + kq * 4;
            uint2 v = make_uint2(0u, 0u);
            if (i < Nn) {
                if (R == 0) {
                    if (kg < 128) v = (hh ? d_Qh : d_Ph)[i * 32 + (kg >> 2)];
                    else          v = d_Xh[i * 32 + ((kg - 128) >> 2)];
                } else {
                    if (kg < 64)       v = d_Ph[i * 32 + hh * 16 + (kg >> 2)];
                    else if (kg < 128) v = d_Qh[i * 32 + (1 - hh) * 16 + ((kg - 64) >> 2)];
                    else               v = ((R == 1) ? d_Zh1 : d_Zh2)[i * 32 + hh * 16 + ((kg - 128) >> 2)];
                }
            }
            *(uint2*)&Ash[hh][m][kq * 4] = v;
        }
        __syncthreads();

        for (int s = 0; s < SL / 16; s++) {
            unsigned a[4][4];
            #pragma unroll
            for (int mt = 0; mt < 4; mt++) {
                int row  = mt * 16 + (lane & 15);
                int kcol = s * 16 + ((lane >> 4) & 1) * 8;
                ldsm4(a[mt], smem_u32(&Ash[h][row][kcol]));
            }
            const int kglob = ks + s * 16;
            #pragma unroll
            for (int sp = 0; sp < 2; sp++) {
                int n = h * 64 + wl * 16 + sp * 8 + grp;
                #pragma unroll
                for (int ps = 0; ps < 2; ps++) {
                    const __half* Wb = d_Wt + (((R * 2 + ps) * 128 + n) * 256) + kglob + tg * 2;
                    unsigned b0 = *(const unsigned*)(Wb);
                    unsigned b1 = *(const unsigned*)(Wb + 8);
                    #pragma unroll
                    for (int mt = 0; mt < 4; mt++)
                        mma16816(acc[mt][sp], a[mt], b0, b1);
                }
            }
        }
    }

    // epilogue: bias + tanh -> z fp16 mirror (R<2) or d_out fp32 (R==2)
    __half* Zm = (R == 0) ? (__half*)d_Zh1 : (__half*)d_Zh2;
    #pragma unroll
    for (int mt = 0; mt < 4; mt++) {
        #pragma unroll
        for (int sp = 0; sp < 2; sp++) {
            int col = h * 64 + wl * 16 + sp * 8 + tg * 2;
            float b0 = d_bias[R * 128 + col];
            float b1 = d_bias[R * 128 + col + 1];
            #pragma unroll
            for (int rr = 0; rr < 2; rr++) {
                int row = base + mt * 16 + grp + rr * 8;
                if (row < Nn) {
                    float t0 = tanhf(acc[mt][sp][rr * 2 + 0] + b0);
                    float t1 = tanhf(acc[mt][sp][rr * 2 + 1] + b1);
                    if (R == 2) {
                        *(float2*)&outp[(long)row * 128 + col] = make_float2(t0, t1);
                    } else {
                        __half2 hv = __floats2half2_rn(t0, t1);
                        *(__half2*)(Zm + (long)row * 128 + col) = hv;
                    }
                }
            }
        }
    }
}

// ---------------- launch (kernel launches only; graph-capturable) ----------------
extern "C" void kernel_launch(void* const* d_in, const int* in_sizes, int n_in,
                              void* d_out, int out_size) {
    const float* x      = (const float*)d_in[0];
    const void*  pe     = d_in[1];
    const void*  ne     = d_in[2];
    const float* Wp_l   = (const float*)d_in[3];
    const float* Wp_r   = (const float*)d_in[4];
    const float* bp     = (const float*)d_in[5];
    const float* Wn_l   = (const float*)d_in[6];
    const float* Wn_r   = (const float*)d_in[7];
    const float* bn     = (const float*)d_in[8];
    const float* Wl_pos = (const float*)d_in[9];
    const float* Wr_pos = (const float*)d_in[10];
    const float* b_pos  = (const float*)d_in[11];
    const float* Wl_neg = (const float*)d_in[12];
    const float* Wr_neg = (const float*)d_in[13];
    const float* b_neg  = (const float*)d_in[14];

    const float4* xin  = (const float4*)x;
    float*        outp = (float*)d_out;

    // prep + CSR build
    k_detect<<<1, 256>>>((const int*)pe);
    k_x2h  <<<(Nn * 32 + 255) / 256, 256>>>(xin);
    k_wprep<<<(3 * 128 * 256 + 255) / 256, 256>>>(Wp_l, Wp_r, bp, Wn_l, Wn_r, bn,
                                                  Wl_pos, Wr_pos, b_pos, Wl_neg, Wr_neg, b_neg);
    k_zero <<<(2 * Nn + 255) / 256, 256>>>();
    k_hist <<<(2 * Ee + 255) / 256, 256>>>(pe, ne);
    k_scan1<<<dim3(98, 2), 1024>>>();
    k_scan2<<<dim3(1, 2), 128>>>();
    k_scan3<<<dim3((Nn + 255) / 256, 2), 256>>>();
    k_fill <<<(2 * Ee + 255) / 256, 256>>>(pe, ne);

    const int MGRID = (Nn + 63) / 64;   // 1563

    // round 0
    k_agg<<<dim3(Nn / 4, 2), 128>>>(0);
    k_mm<0><<<MGRID, 256>>>(outp);
    // round 1
    k_agg<<<dim3(Nn / 4, 2), 128>>>(1);
    k_mm<1><<<MGRID, 256>>>(outp);
    // round 2 -> d_out
    k_agg<<<dim3(Nn / 4, 2), 128>>>(2);
    k_mm<2><<<MGRID, 256>>>(outp);
}